// round 5
// baseline (speedup 1.0000x reference)
#include <cuda_runtime.h>
#include <math.h>
#include <stdint.h>

// ---------------------------------------------------------------------------
// Shapes: x (N=2, T=2048, C=512), H=8, hd=64, WIN=63, LEFT=31, hid=2048
// ---------------------------------------------------------------------------
#define C_DIM   512
#define HID_DIM 2048
#define QKV_DIM 1536
#define HEAD_D  64
#define WIN     63
#define LEFT    31
#define M_ROWS  4096

#define PAD 20          // GEMM smem row stride (floats)

// attention tiling
#define ATT_TT   64
#define ATT_SPAN (ATT_TT + WIN - 1) // 126
#define ATT_LD   65

// ---------------------------------------------------------------------------
// Scratch
// ---------------------------------------------------------------------------
__device__ float g_h  [M_ROWS * C_DIM];
__device__ float g_qkv[M_ROWS * QKV_DIM];
__device__ float g_att[M_ROWS * C_DIM];
__device__ float g_x2 [M_ROWS * C_DIM];
__device__ float g_m1 [M_ROWS * HID_DIM];

// ---------------------------------------------------------------------------
// PTX helpers
// ---------------------------------------------------------------------------
__device__ __forceinline__ void cp_async16(void* smem, const void* gmem) {
    uint32_t s = (uint32_t)__cvta_generic_to_shared(smem);
    asm volatile("cp.async.cg.shared.global [%0], [%1], 16;\n" :: "r"(s), "l"(gmem));
}
__device__ __forceinline__ void mma_tf32(float* c, const uint32_t* a, const uint32_t* b) {
    asm volatile(
        "mma.sync.aligned.m16n8k8.row.col.f32.tf32.tf32.f32 "
        "{%0,%1,%2,%3}, {%4,%5,%6,%7}, {%8,%9}, {%0,%1,%2,%3};\n"
        : "+f"(c[0]), "+f"(c[1]), "+f"(c[2]), "+f"(c[3])
        : "r"(a[0]), "r"(a[1]), "r"(a[2]), "r"(a[3]), "r"(b[0]), "r"(b[1]));
}

// ---------------------------------------------------------------------------
// LayerNorm: one block (128 threads) per row of 512 floats
// ---------------------------------------------------------------------------
__global__ __launch_bounds__(128) void ln_kernel(
    const float* __restrict__ x, const float* __restrict__ w,
    const float* __restrict__ b, float* __restrict__ out)
{
    int row = blockIdx.x;
    int tid = threadIdx.x;
    const float4* xr = (const float4*)(x + (size_t)row * C_DIM);
    float4 v = xr[tid];
    float s  = v.x + v.y + v.z + v.w;
    float sq = v.x*v.x + v.y*v.y + v.z*v.z + v.w*v.w;
    #pragma unroll
    for (int o = 16; o > 0; o >>= 1) {
        s  += __shfl_xor_sync(0xffffffffu, s,  o);
        sq += __shfl_xor_sync(0xffffffffu, sq, o);
    }
    __shared__ float ss[4], ssq[4];
    if ((tid & 31) == 0) { ss[tid >> 5] = s; ssq[tid >> 5] = sq; }
    __syncthreads();
    s  = ss[0]  + ss[1]  + ss[2]  + ss[3];
    sq = ssq[0] + ssq[1] + ssq[2] + ssq[3];
    float mu  = s * (1.0f / C_DIM);
    float var = sq * (1.0f / C_DIM) - mu * mu;
    float inv = rsqrtf(var + 1e-5f);
    float4 wv = ((const float4*)w)[tid];
    float4 bv = ((const float4*)b)[tid];
    float4 o;
    o.x = (v.x - mu) * inv * wv.x + bv.x;
    o.y = (v.y - mu) * inv * wv.y + bv.y;
    o.z = (v.z - mu) * inv * wv.z + bv.z;
    o.w = (v.w - mu) * inv * wv.w + bv.w;
    ((float4*)(out + (size_t)row * C_DIM))[tid] = o;
}

// ---------------------------------------------------------------------------
// TF32 tensor-core GEMM: C[M,N] = A[M,K] @ B[N,K]^T + bias (+res) (opt GELU)
// BM=64, BN=128, BK=16, 256 threads = 8 warps (2 M x 4 N), warp tile 32x32.
// 3-stage cp.async pipeline, ONE __syncthreads per K-iter, 3 CTAs/SM.
// fp32 bits fed directly to HMMA.TF32 (HW truncates mantissa).
// ---------------------------------------------------------------------------
template<bool RES, bool GELU>
__global__ __launch_bounds__(256, 3) void tc_gemm(
    const float* __restrict__ A, const float* __restrict__ B,
    const float* __restrict__ bias, const float* __restrict__ res,
    float* __restrict__ Cm, int M, int N, int K)
{
    constexpr int BM = 64, BN = 128, BK = 16, ST = 3;
    constexpr int MT = 2;            // two m16 tiles per warp (32 rows)

    __shared__ __align__(16) float smA[ST][BM * PAD];
    __shared__ __align__(16) float smB[ST][BN * PAD];

    const int tid    = threadIdx.x;
    const int wid    = tid >> 5;
    const int lane   = tid & 31;
    const int g      = lane >> 2;
    const int tg     = lane & 3;
    const int warp_m = wid & 1;      // 0..1 -> 32 rows
    const int warp_n = wid >> 1;     // 0..3 -> 32 cols

    const float* Ab = A + (size_t)blockIdx.y * BM * K;
    const float* Bb = B + (size_t)blockIdx.x * BN * K;

    float acc[MT][4][4];
    #pragma unroll
    for (int mt = 0; mt < MT; mt++)
        #pragma unroll
        for (int nt = 0; nt < 4; nt++)
            #pragma unroll
            for (int i = 0; i < 4; i++) acc[mt][nt][i] = 0.0f;

    // per chunk: A 64 rows x 16 f = 256 float4 (1/thread); B 128 rows = 512 (2/thread)
    const int arow = tid >> 2;
    const int aq   = (tid & 3) << 2;
    auto load_chunk = [&](int buf, int k0) {
        cp_async16(&smA[buf][arow * PAD + aq], Ab + (size_t)arow * K + k0 + aq);
        #pragma unroll
        for (int it = 0; it < 2; ++it) {
            int i = tid + it * 256;
            int r = i >> 2;
            int q = (i & 3) << 2;
            cp_async16(&smB[buf][r * PAD + q], Bb + (size_t)r * K + k0 + q);
        }
    };

    const int nch = K / BK;          // >= 32 here
    load_chunk(0, 0);
    asm volatile("cp.async.commit_group;");
    load_chunk(1, BK);
    asm volatile("cp.async.commit_group;");

    for (int c = 0; c < nch; ++c) {
        asm volatile("cp.async.wait_group 1;");   // stage c landed
        __syncthreads();                          // visible to all; prev compute done

        if (c + 2 < nch) load_chunk((c + 2) % ST, (c + 2) * BK);
        asm volatile("cp.async.commit_group;");   // uniform group count

        const float* sa = smA[c % ST];
        const float* sb = smB[c % ST];

        #pragma unroll
        for (int ks = 0; ks < 2; ++ks) {
            const int k0 = ks * 8;
            uint32_t af[MT][4], bf[4][2];
            #pragma unroll
            for (int mt = 0; mt < MT; ++mt) {
                const float* p = sa + (warp_m * 32 + mt * 16 + g) * PAD + k0;
                af[mt][0] = __float_as_uint(p[tg]);
                af[mt][1] = __float_as_uint(p[8 * PAD + tg]);
                af[mt][2] = __float_as_uint(p[tg + 4]);
                af[mt][3] = __float_as_uint(p[8 * PAD + tg + 4]);
            }
            #pragma unroll
            for (int nt = 0; nt < 4; ++nt) {
                const float* p = sb + (warp_n * 32 + nt * 8 + g) * PAD + k0;
                bf[nt][0] = __float_as_uint(p[tg]);
                bf[nt][1] = __float_as_uint(p[tg + 4]);
            }
            #pragma unroll
            for (int mt = 0; mt < MT; ++mt)
                #pragma unroll
                for (int nt = 0; nt < 4; ++nt)
                    mma_tf32(acc[mt][nt], af[mt], bf[nt]);
        }
    }

    const int row_base = blockIdx.y * BM + warp_m * 32;
    const int col_base = blockIdx.x * BN + warp_n * 32;
    #pragma unroll
    for (int mt = 0; mt < MT; ++mt) {
        #pragma unroll
        for (int nt = 0; nt < 4; ++nt) {
            int r0 = row_base + mt * 16 + g;
            int c0 = col_base + nt * 8 + 2 * tg;
            float b0 = bias[c0], b1 = bias[c0 + 1];
            #pragma unroll
            for (int half = 0; half < 2; ++half) {
                int r = r0 + half * 8;
                float v0 = acc[mt][nt][half * 2 + 0] + b0;
                float v1 = acc[mt][nt][half * 2 + 1] + b1;
                size_t off = (size_t)r * N + c0;
                if (RES) {
                    float2 rv = *(const float2*)(res + off);
                    v0 += rv.x; v1 += rv.y;
                }
                if (GELU) {
                    v0 = 0.5f * v0 * (1.0f + erff(v0 * 0.70710678118654752f));
                    v1 = 0.5f * v1 * (1.0f + erff(v1 * 0.70710678118654752f));
                }
                float2 ov; ov.x = v0; ov.y = v1;
                *(float2*)(Cm + off) = ov;
            }
        }
    }
}

// ---------------------------------------------------------------------------
// Tiled windowed attention: block = 64 tokens x 1 head (as R4, passed)
// ---------------------------------------------------------------------------
__global__ __launch_bounds__(256) void attn_kernel(
    const float* __restrict__ qkv, const float* __restrict__ rel_bias,
    float* __restrict__ out, int T)
{
    const int t0 = blockIdx.x * ATT_TT;
    const int h  = blockIdx.y;
    const int n  = blockIdx.z;
    const int tid  = threadIdx.x;
    const int wid  = tid >> 5;
    const int lane = tid & 31;

    extern __shared__ __align__(16) float sm[];
    float* sk = sm;
    float* sv = sk + ATT_SPAN * ATT_LD;
    float* sq = sv + ATT_SPAN * ATT_LD;

    for (int i = tid; i < ATT_SPAN * 16; i += 256) {
        int j  = i >> 4;
        int f4 = (i & 15) << 2;
        int pos = t0 - LEFT + j;
        float4 kv, vv;
        if (pos >= 0 && pos < T) {
            const float* base = qkv + ((size_t)n * T + pos) * QKV_DIM + h * HEAD_D;
            kv = *(const float4*)(base + C_DIM + f4);
            vv = *(const float4*)(base + 2 * C_DIM + f4);
        } else {
            kv = make_float4(0.f, 0.f, 0.f, 0.f);
            vv = make_float4(0.f, 0.f, 0.f, 0.f);
        }
        float* kd = sk + j * ATT_LD + f4;
        float* vd = sv + j * ATT_LD + f4;
        kd[0] = kv.x; kd[1] = kv.y; kd[2] = kv.z; kd[3] = kv.w;
        vd[0] = vv.x; vd[1] = vv.y; vd[2] = vv.z; vd[3] = vv.w;
    }
    for (int i = tid; i < ATT_TT * 16; i += 256) {
        int j  = i >> 4;
        int f4 = (i & 15) << 2;
        const float* base = qkv + ((size_t)n * T + t0 + j) * QKV_DIM + h * HEAD_D;
        float4 qv = *(const float4*)(base + f4);
        float* qd = sq + j * ATT_LD + f4;
        qd[0] = qv.x * 0.125f; qd[1] = qv.y * 0.125f;
        qd[2] = qv.z * 0.125f; qd[3] = qv.w * 0.125f;
    }
    __syncthreads();

    const float bias0 = rel_bias[h * WIN + lane];
    const float bias1 = (lane < WIN - 32) ? rel_bias[h * WIN + lane + 32] : 0.0f;

    #pragma unroll 1
    for (int tt = 0; tt < 8; ++tt) {
        const int tok = wid * 8 + tt;
        const int t   = t0 + tok;
        const float* qrow = sq + tok * ATT_LD;

        float p0, p1;
        {
            int pos = t - LEFT + lane;
            if (pos >= 0 && pos < T) {
                const float* kr = sk + (tok + lane) * ATT_LD;
                float dot = 0.f;
                #pragma unroll
                for (int d = 0; d < HEAD_D; d += 4) {
                    dot += qrow[d]   * kr[d]   + qrow[d+1] * kr[d+1]
                         + qrow[d+2] * kr[d+2] + qrow[d+3] * kr[d+3];
                }
                p0 = dot + bias0;
            } else {
                p0 = bias0 - 100.0f;
            }
        }
        if (lane < WIN - 32) {
            int pos = t - LEFT + lane + 32;
            if (pos >= 0 && pos < T) {
                const float* kr = sk + (tok + lane + 32) * ATT_LD;
                float dot = 0.f;
                #pragma unroll
                for (int d = 0; d < HEAD_D; d += 4) {
                    dot += qrow[d]   * kr[d]   + qrow[d+1] * kr[d+1]
                         + qrow[d+2] * kr[d+2] + qrow[d+3] * kr[d+3];
                }
                p1 = dot + bias1;
            } else {
                p1 = bias1 - 100.0f;
            }
        } else {
            p1 = -1e30f;
        }

        float mx = fmaxf(p0, p1);
        #pragma unroll
        for (int o = 16; o > 0; o >>= 1)
            mx = fmaxf(mx, __shfl_xor_sync(0xffffffffu, mx, o));
        float e0 = expf(p0 - mx);
        float e1 = (lane < WIN - 32) ? expf(p1 - mx) : 0.0f;
        float sum = e0 + e1;
        #pragma unroll
        for (int o = 16; o > 0; o >>= 1)
            sum += __shfl_xor_sync(0xffffffffu, sum, o);
        float rinv = 1.0f / sum;
        e0 *= rinv; e1 *= rinv;

        float acc0 = 0.f, acc1 = 0.f;
        #pragma unroll
        for (int w = 0; w < WIN; ++w) {
            float a = __shfl_sync(0xffffffffu, (w < 32) ? e0 : e1, w & 31);
            const float* vr = sv + (tok + w) * ATT_LD;
            acc0 += a * vr[lane];
            acc1 += a * vr[lane + 32];
        }
        float* orow = out + ((size_t)n * T + t) * C_DIM + h * HEAD_D;
        orow[lane]      = acc0;
        orow[lane + 32] = acc1;
    }
}

// ---------------------------------------------------------------------------
// Launch
// ---------------------------------------------------------------------------
extern "C" void kernel_launch(void* const* d_in, const int* in_sizes, int n_in,
                              void* d_out, int out_size)
{
    const float* x       = (const float*)d_in[0];
    const float* norm1_w = (const float*)d_in[1];
    const float* norm1_b = (const float*)d_in[2];
    const float* qkv_w   = (const float*)d_in[3];
    const float* qkv_b   = (const float*)d_in[4];
    const float* relbias = (const float*)d_in[5];
    const float* proj_w  = (const float*)d_in[6];
    const float* proj_b  = (const float*)d_in[7];
    const float* norm2_w = (const float*)d_in[8];
    const float* norm2_b = (const float*)d_in[9];
    const float* fc1_w   = (const float*)d_in[10];
    const float* fc1_b   = (const float*)d_in[11];
    const float* fc2_w   = (const float*)d_in[12];
    const float* fc2_b   = (const float*)d_in[13];
    float* out = (float*)d_out;

    int M = in_sizes[0] / C_DIM;   // 4096
    int Nb = 2;
    int T = M / Nb;                // 2048

    float *p_h, *p_qkv, *p_att, *p_x2, *p_m1;
    cudaGetSymbolAddress((void**)&p_h,   g_h);
    cudaGetSymbolAddress((void**)&p_qkv, g_qkv);
    cudaGetSymbolAddress((void**)&p_att, g_att);
    cudaGetSymbolAddress((void**)&p_x2,  g_x2);
    cudaGetSymbolAddress((void**)&p_m1,  g_m1);

    const int ATT_SMEM = (2 * ATT_SPAN * ATT_LD + ATT_TT * ATT_LD) * 4;
    cudaFuncSetAttribute(attn_kernel,
        cudaFuncAttributeMaxDynamicSharedMemorySize, ATT_SMEM);

    // 1) h = LN1(x)
    ln_kernel<<<M, 128>>>(x, norm1_w, norm1_b, p_h);

    // 2) qkv = h @ qkv_w^T + qkv_b        [M,1536]
    tc_gemm<false, false><<<dim3(QKV_DIM / 128, M / 64), 256>>>(
        p_h, qkv_w, qkv_b, nullptr, p_qkv, M, QKV_DIM, C_DIM);

    // 3) windowed attention -> g_att      [M,512]
    attn_kernel<<<dim3(T / ATT_TT, 8, Nb), 256, ATT_SMEM>>>(
        p_qkv, relbias, p_att, T);

    // 4) x2 = x + att @ proj_w^T + proj_b [M,512]
    tc_gemm<true, false><<<dim3(C_DIM / 128, M / 64), 256>>>(
        p_att, proj_w, proj_b, x, p_x2, M, C_DIM, C_DIM);

    // 5) h = LN2(x2)
    ln_kernel<<<M, 128>>>(p_x2, norm2_w, norm2_b, p_h);

    // 6) m1 = gelu(h @ fc1_w^T + fc1_b)   [M,2048]
    tc_gemm<false, true><<<dim3(HID_DIM / 128, M / 64), 256>>>(
        p_h, fc1_w, fc1_b, nullptr, p_m1, M, HID_DIM, C_DIM);

    // 7) out = x2 + m1 @ fc2_w^T + fc2_b  [M,512]
    tc_gemm<true, false><<<dim3(C_DIM / 128, M / 64), 256>>>(
        p_m1, fc2_w, fc2_b, p_x2, out, M, C_DIM, HID_DIM);
}

// round 6
// speedup vs baseline: 1.1008x; 1.1008x over previous
#include <cuda_runtime.h>
#include <math.h>
#include <stdint.h>

// ---------------------------------------------------------------------------
// Shapes: x (N=2, T=2048, C=512), H=8, hd=64, WIN=63, LEFT=31, hid=2048
// ---------------------------------------------------------------------------
#define C_DIM   512
#define HID_DIM 2048
#define QKV_DIM 1536
#define HEAD_D  64
#define WIN     63
#define LEFT    31
#define M_ROWS  4096

#define PAD 20          // smem row stride for BK=16 kernels
#define PADB 36         // smem row stride for BK=32 kernel

// attention tiling
#define ATT_TT   64
#define ATT_SPAN (ATT_TT + WIN - 1) // 126
#define ATT_LD   65

// ---------------------------------------------------------------------------
// Scratch
// ---------------------------------------------------------------------------
__device__ float g_h   [M_ROWS * C_DIM];
__device__ float g_qkv [M_ROWS * QKV_DIM];
__device__ float g_att [M_ROWS * C_DIM];
__device__ float g_x2  [M_ROWS * C_DIM];
__device__ float g_m1  [M_ROWS * HID_DIM];
__device__ float g_part[2 * M_ROWS * C_DIM];   // split-K partials

// ---------------------------------------------------------------------------
// PTX helpers
// ---------------------------------------------------------------------------
__device__ __forceinline__ void cp_async16(void* smem, const void* gmem) {
    uint32_t s = (uint32_t)__cvta_generic_to_shared(smem);
    asm volatile("cp.async.cg.shared.global [%0], [%1], 16;\n" :: "r"(s), "l"(gmem));
}
__device__ __forceinline__ void mma_tf32(float* c, const uint32_t* a, const uint32_t* b) {
    asm volatile(
        "mma.sync.aligned.m16n8k8.row.col.f32.tf32.tf32.f32 "
        "{%0,%1,%2,%3}, {%4,%5,%6,%7}, {%8,%9}, {%0,%1,%2,%3};\n"
        : "+f"(c[0]), "+f"(c[1]), "+f"(c[2]), "+f"(c[3])
        : "r"(a[0]), "r"(a[1]), "r"(a[2]), "r"(a[3]), "r"(b[0]), "r"(b[1]));
}

// ---------------------------------------------------------------------------
// LayerNorm
// ---------------------------------------------------------------------------
__global__ __launch_bounds__(128) void ln_kernel(
    const float* __restrict__ x, const float* __restrict__ w,
    const float* __restrict__ b, float* __restrict__ out)
{
    int row = blockIdx.x;
    int tid = threadIdx.x;
    const float4* xr = (const float4*)(x + (size_t)row * C_DIM);
    float4 v = xr[tid];
    float s  = v.x + v.y + v.z + v.w;
    float sq = v.x*v.x + v.y*v.y + v.z*v.z + v.w*v.w;
    #pragma unroll
    for (int o = 16; o > 0; o >>= 1) {
        s  += __shfl_xor_sync(0xffffffffu, s,  o);
        sq += __shfl_xor_sync(0xffffffffu, sq, o);
    }
    __shared__ float ss[4], ssq[4];
    if ((tid & 31) == 0) { ss[tid >> 5] = s; ssq[tid >> 5] = sq; }
    __syncthreads();
    s  = ss[0]  + ss[1]  + ss[2]  + ss[3];
    sq = ssq[0] + ssq[1] + ssq[2] + ssq[3];
    float mu  = s * (1.0f / C_DIM);
    float var = sq * (1.0f / C_DIM) - mu * mu;
    float inv = rsqrtf(var + 1e-5f);
    float4 wv = ((const float4*)w)[tid];
    float4 bv = ((const float4*)b)[tid];
    float4 o;
    o.x = (v.x - mu) * inv * wv.x + bv.x;
    o.y = (v.y - mu) * inv * wv.y + bv.y;
    o.z = (v.z - mu) * inv * wv.z + bv.z;
    o.w = (v.w - mu) * inv * wv.w + bv.w;
    ((float4*)(out + (size_t)row * C_DIM))[tid] = o;
}

// ---------------------------------------------------------------------------
// Big-tile GEMM (qkv, fc1): C = A@B^T + bias (opt GELU)
// BM=128, BN=128, BK=32, 2-stage cp.async, 8 warps (2Mx4N, warp 64x32),
// 2 CTAs/SM, dynamic smem (72 KB).
// ---------------------------------------------------------------------------
template<bool GELU>
__global__ __launch_bounds__(256, 2) void tc_gemm_big(
    const float* __restrict__ A, const float* __restrict__ B,
    const float* __restrict__ bias, float* __restrict__ Cm,
    int M, int N, int K)
{
    constexpr int BM = 128, BN = 128, BK = 32, MT = 4;

    extern __shared__ __align__(16) float dsm[];
    float* smA = dsm;                       // [2][128*PADB]
    float* smB = dsm + 2 * BM * PADB;       // [2][128*PADB]

    const int tid    = threadIdx.x;
    const int wid    = tid >> 5;
    const int lane   = tid & 31;
    const int g      = lane >> 2;
    const int tg     = lane & 3;
    const int warp_m = wid & 1;
    const int warp_n = wid >> 1;

    const float* Ab = A + (size_t)blockIdx.y * BM * K;
    const float* Bb = B + (size_t)blockIdx.x * BN * K;

    float acc[MT][4][4];
    #pragma unroll
    for (int mt = 0; mt < MT; mt++)
        #pragma unroll
        for (int nt = 0; nt < 4; nt++)
            #pragma unroll
            for (int i = 0; i < 4; i++) acc[mt][nt][i] = 0.0f;

    // chunk: 128 rows x 32 floats = 1024 float4 per matrix (4/thread)
    auto load_chunk = [&](int buf, int k0) {
        float* da = smA + buf * BM * PADB;
        float* db = smB + buf * BN * PADB;
        #pragma unroll
        for (int it = 0; it < 4; ++it) {
            int i = tid + it * 256;
            int r = i >> 3;
            int q = (i & 7) << 2;
            cp_async16(&da[r * PADB + q], Ab + (size_t)r * K + k0 + q);
        }
        #pragma unroll
        for (int it = 0; it < 4; ++it) {
            int i = tid + it * 256;
            int r = i >> 3;
            int q = (i & 7) << 2;
            cp_async16(&db[r * PADB + q], Bb + (size_t)r * K + k0 + q);
        }
    };

    const int nch = K / BK;
    load_chunk(0, 0);
    asm volatile("cp.async.commit_group;");

    for (int c = 0; c < nch; ++c) {
        if (c + 1 < nch) {
            load_chunk((c + 1) & 1, (c + 1) * BK);
            asm volatile("cp.async.commit_group;");
            asm volatile("cp.async.wait_group 1;");
        } else {
            asm volatile("cp.async.wait_group 0;");
        }
        __syncthreads();

        const float* sa = smA + (c & 1) * BM * PADB;
        const float* sb = smB + (c & 1) * BN * PADB;

        #pragma unroll
        for (int ks = 0; ks < 4; ++ks) {
            const int k0 = ks * 8;
            uint32_t af[MT][4], bf[4][2];
            #pragma unroll
            for (int mt = 0; mt < MT; ++mt) {
                const float* p = sa + (warp_m * 64 + mt * 16 + g) * PADB + k0;
                af[mt][0] = __float_as_uint(p[tg]);
                af[mt][1] = __float_as_uint(p[8 * PADB + tg]);
                af[mt][2] = __float_as_uint(p[tg + 4]);
                af[mt][3] = __float_as_uint(p[8 * PADB + tg + 4]);
            }
            #pragma unroll
            for (int nt = 0; nt < 4; ++nt) {
                const float* p = sb + (warp_n * 32 + nt * 8 + g) * PADB + k0;
                bf[nt][0] = __float_as_uint(p[tg]);
                bf[nt][1] = __float_as_uint(p[tg + 4]);
            }
            #pragma unroll
            for (int mt = 0; mt < MT; ++mt)
                #pragma unroll
                for (int nt = 0; nt < 4; ++nt)
                    mma_tf32(acc[mt][nt], af[mt], bf[nt]);
        }
        __syncthreads();
    }

    const int row_base = blockIdx.y * BM + warp_m * 64;
    const int col_base = blockIdx.x * BN + warp_n * 32;
    #pragma unroll
    for (int mt = 0; mt < MT; ++mt) {
        #pragma unroll
        for (int nt = 0; nt < 4; ++nt) {
            int r0 = row_base + mt * 16 + g;
            int c0 = col_base + nt * 8 + 2 * tg;
            float b0 = bias[c0], b1 = bias[c0 + 1];
            #pragma unroll
            for (int half = 0; half < 2; ++half) {
                int r = r0 + half * 8;
                float v0 = acc[mt][nt][half * 2 + 0] + b0;
                float v1 = acc[mt][nt][half * 2 + 1] + b1;
                if (GELU) {
                    v0 = 0.5f * v0 * (1.0f + erff(v0 * 0.70710678118654752f));
                    v1 = 0.5f * v1 * (1.0f + erff(v1 * 0.70710678118654752f));
                }
                float2 ov; ov.x = v0; ov.y = v1;
                *(float2*)(Cm + (size_t)r * N + c0) = ov;
            }
        }
    }
}

// ---------------------------------------------------------------------------
// Split-K GEMM (proj, fc2): partial[z] = A[:, zKh:(z+1)Kh] @ B[:, zKh:..]^T
// BM=64, BN=128, BK=16, 3-stage, (256,3). Raw partials, no epilogue.
// grid (N/128, M/64, 2)
// ---------------------------------------------------------------------------
__global__ __launch_bounds__(256, 3) void tc_gemm_sk(
    const float* __restrict__ A, const float* __restrict__ B,
    float* __restrict__ part, int M, int N, int K)
{
    constexpr int BM = 64, BN = 128, BK = 16, ST = 3;
    constexpr int MT = 2;

    __shared__ __align__(16) float smA[ST][BM * PAD];
    __shared__ __align__(16) float smB[ST][BN * PAD];

    const int tid    = threadIdx.x;
    const int wid    = tid >> 5;
    const int lane   = tid & 31;
    const int g      = lane >> 2;
    const int tg     = lane & 3;
    const int warp_m = wid & 1;
    const int warp_n = wid >> 1;

    const int Kh = K >> 1;
    const int z  = blockIdx.z;

    const float* Ab = A + (size_t)blockIdx.y * BM * K + (size_t)z * Kh;
    const float* Bb = B + (size_t)blockIdx.x * BN * K + (size_t)z * Kh;

    float acc[MT][4][4];
    #pragma unroll
    for (int mt = 0; mt < MT; mt++)
        #pragma unroll
        for (int nt = 0; nt < 4; nt++)
            #pragma unroll
            for (int i = 0; i < 4; i++) acc[mt][nt][i] = 0.0f;

    const int arow = tid >> 2;
    const int aq   = (tid & 3) << 2;
    auto load_chunk = [&](int buf, int k0) {
        cp_async16(&smA[buf][arow * PAD + aq], Ab + (size_t)arow * K + k0 + aq);
        #pragma unroll
        for (int it = 0; it < 2; ++it) {
            int i = tid + it * 256;
            int r = i >> 2;
            int q = (i & 3) << 2;
            cp_async16(&smB[buf][r * PAD + q], Bb + (size_t)r * K + k0 + q);
        }
    };

    const int nch = Kh / BK;
    load_chunk(0, 0);
    asm volatile("cp.async.commit_group;");
    load_chunk(1, BK);
    asm volatile("cp.async.commit_group;");

    for (int c = 0; c < nch; ++c) {
        asm volatile("cp.async.wait_group 1;");
        __syncthreads();

        if (c + 2 < nch) load_chunk((c + 2) % ST, (c + 2) * BK);
        asm volatile("cp.async.commit_group;");

        const float* sa = smA[c % ST];
        const float* sb = smB[c % ST];

        #pragma unroll
        for (int ks = 0; ks < 2; ++ks) {
            const int k0 = ks * 8;
            uint32_t af[MT][4], bf[4][2];
            #pragma unroll
            for (int mt = 0; mt < MT; ++mt) {
                const float* p = sa + (warp_m * 32 + mt * 16 + g) * PAD + k0;
                af[mt][0] = __float_as_uint(p[tg]);
                af[mt][1] = __float_as_uint(p[8 * PAD + tg]);
                af[mt][2] = __float_as_uint(p[tg + 4]);
                af[mt][3] = __float_as_uint(p[8 * PAD + tg + 4]);
            }
            #pragma unroll
            for (int nt = 0; nt < 4; ++nt) {
                const float* p = sb + (warp_n * 32 + nt * 8 + g) * PAD + k0;
                bf[nt][0] = __float_as_uint(p[tg]);
                bf[nt][1] = __float_as_uint(p[tg + 4]);
            }
            #pragma unroll
            for (int mt = 0; mt < MT; ++mt)
                #pragma unroll
                for (int nt = 0; nt < 4; ++nt)
                    mma_tf32(acc[mt][nt], af[mt], bf[nt]);
        }
    }

    float* po = part + (size_t)z * M * N;
    const int row_base = blockIdx.y * BM + warp_m * 32;
    const int col_base = blockIdx.x * BN + warp_n * 32;
    #pragma unroll
    for (int mt = 0; mt < MT; ++mt) {
        #pragma unroll
        for (int nt = 0; nt < 4; ++nt) {
            int r0 = row_base + mt * 16 + g;
            int c0 = col_base + nt * 8 + 2 * tg;
            #pragma unroll
            for (int half = 0; half < 2; ++half) {
                int r = r0 + half * 8;
                float2 ov;
                ov.x = acc[mt][nt][half * 2 + 0];
                ov.y = acc[mt][nt][half * 2 + 1];
                *(float2*)(po + (size_t)r * N + c0) = ov;
            }
        }
    }
}

// ---------------------------------------------------------------------------
// Split-K combine: out = p0 + p1 + bias + res   (N = C_DIM = 512, pow2)
// ---------------------------------------------------------------------------
__global__ __launch_bounds__(256) void sk_combine(
    const float* __restrict__ part, const float* __restrict__ bias,
    const float* __restrict__ res, float* __restrict__ out, int total4)
{
    int i = blockIdx.x * 256 + threadIdx.x;
    if (i >= total4) return;
    int col = (i << 2) & (C_DIM - 1);
    float4 p0 = ((const float4*)part)[i];
    float4 p1 = ((const float4*)part)[i + (M_ROWS * C_DIM / 4)];
    float4 bv = *(const float4*)(bias + col);
    float4 rv = ((const float4*)res)[i];
    float4 o;
    o.x = p0.x + p1.x + bv.x + rv.x;
    o.y = p0.y + p1.y + bv.y + rv.y;
    o.z = p0.z + p1.z + bv.z + rv.z;
    o.w = p0.w + p1.w + bv.w + rv.w;
    ((float4*)out)[i] = o;
}

// ---------------------------------------------------------------------------
// Tiled windowed attention (R4-proven)
// ---------------------------------------------------------------------------
__global__ __launch_bounds__(256) void attn_kernel(
    const float* __restrict__ qkv, const float* __restrict__ rel_bias,
    float* __restrict__ out, int T)
{
    const int t0 = blockIdx.x * ATT_TT;
    const int h  = blockIdx.y;
    const int n  = blockIdx.z;
    const int tid  = threadIdx.x;
    const int wid  = tid >> 5;
    const int lane = tid & 31;

    extern __shared__ __align__(16) float sm[];
    float* sk = sm;
    float* sv = sk + ATT_SPAN * ATT_LD;
    float* sq = sv + ATT_SPAN * ATT_LD;

    for (int i = tid; i < ATT_SPAN * 16; i += 256) {
        int j  = i >> 4;
        int f4 = (i & 15) << 2;
        int pos = t0 - LEFT + j;
        float4 kv, vv;
        if (pos >= 0 && pos < T) {
            const float* base = qkv + ((size_t)n * T + pos) * QKV_DIM + h * HEAD_D;
            kv = *(const float4*)(base + C_DIM + f4);
            vv = *(const float4*)(base + 2 * C_DIM + f4);
        } else {
            kv = make_float4(0.f, 0.f, 0.f, 0.f);
            vv = make_float4(0.f, 0.f, 0.f, 0.f);
        }
        float* kd = sk + j * ATT_LD + f4;
        float* vd = sv + j * ATT_LD + f4;
        kd[0] = kv.x; kd[1] = kv.y; kd[2] = kv.z; kd[3] = kv.w;
        vd[0] = vv.x; vd[1] = vv.y; vd[2] = vv.z; vd[3] = vv.w;
    }
    for (int i = tid; i < ATT_TT * 16; i += 256) {
        int j  = i >> 4;
        int f4 = (i & 15) << 2;
        const float* base = qkv + ((size_t)n * T + t0 + j) * QKV_DIM + h * HEAD_D;
        float4 qv = *(const float4*)(base + f4);
        float* qd = sq + j * ATT_LD + f4;
        qd[0] = qv.x * 0.125f; qd[1] = qv.y * 0.125f;
        qd[2] = qv.z * 0.125f; qd[3] = qv.w * 0.125f;
    }
    __syncthreads();

    const float bias0 = rel_bias[h * WIN + lane];
    const float bias1 = (lane < WIN - 32) ? rel_bias[h * WIN + lane + 32] : 0.0f;

    #pragma unroll 1
    for (int tt = 0; tt < 8; ++tt) {
        const int tok = wid * 8 + tt;
        const int t   = t0 + tok;
        const float* qrow = sq + tok * ATT_LD;

        float p0, p1;
        {
            int pos = t - LEFT + lane;
            if (pos >= 0 && pos < T) {
                const float* kr = sk + (tok + lane) * ATT_LD;
                float dot = 0.f;
                #pragma unroll
                for (int d = 0; d < HEAD_D; d += 4) {
                    dot += qrow[d]   * kr[d]   + qrow[d+1] * kr[d+1]
                         + qrow[d+2] * kr[d+2] + qrow[d+3] * kr[d+3];
                }
                p0 = dot + bias0;
            } else {
                p0 = bias0 - 100.0f;
            }
        }
        if (lane < WIN - 32) {
            int pos = t - LEFT + lane + 32;
            if (pos >= 0 && pos < T) {
                const float* kr = sk + (tok + lane + 32) * ATT_LD;
                float dot = 0.f;
                #pragma unroll
                for (int d = 0; d < HEAD_D; d += 4) {
                    dot += qrow[d]   * kr[d]   + qrow[d+1] * kr[d+1]
                         + qrow[d+2] * kr[d+2] + qrow[d+3] * kr[d+3];
                }
                p1 = dot + bias1;
            } else {
                p1 = bias1 - 100.0f;
            }
        } else {
            p1 = -1e30f;
        }

        float mx = fmaxf(p0, p1);
        #pragma unroll
        for (int o = 16; o > 0; o >>= 1)
            mx = fmaxf(mx, __shfl_xor_sync(0xffffffffu, mx, o));
        float e0 = expf(p0 - mx);
        float e1 = (lane < WIN - 32) ? expf(p1 - mx) : 0.0f;
        float sum = e0 + e1;
        #pragma unroll
        for (int o = 16; o > 0; o >>= 1)
            sum += __shfl_xor_sync(0xffffffffu, sum, o);
        float rinv = 1.0f / sum;
        e0 *= rinv; e1 *= rinv;

        float acc0 = 0.f, acc1 = 0.f;
        #pragma unroll
        for (int w = 0; w < WIN; ++w) {
            float a = __shfl_sync(0xffffffffu, (w < 32) ? e0 : e1, w & 31);
            const float* vr = sv + (tok + w) * ATT_LD;
            acc0 += a * vr[lane];
            acc1 += a * vr[lane + 32];
        }
        float* orow = out + ((size_t)n * T + t) * C_DIM + h * HEAD_D;
        orow[lane]      = acc0;
        orow[lane + 32] = acc1;
    }
}

// ---------------------------------------------------------------------------
// Launch
// ---------------------------------------------------------------------------
extern "C" void kernel_launch(void* const* d_in, const int* in_sizes, int n_in,
                              void* d_out, int out_size)
{
    const float* x       = (const float*)d_in[0];
    const float* norm1_w = (const float*)d_in[1];
    const float* norm1_b = (const float*)d_in[2];
    const float* qkv_w   = (const float*)d_in[3];
    const float* qkv_b   = (const float*)d_in[4];
    const float* relbias = (const float*)d_in[5];
    const float* proj_w  = (const float*)d_in[6];
    const float* proj_b  = (const float*)d_in[7];
    const float* norm2_w = (const float*)d_in[8];
    const float* norm2_b = (const float*)d_in[9];
    const float* fc1_w   = (const float*)d_in[10];
    const float* fc1_b   = (const float*)d_in[11];
    const float* fc2_w   = (const float*)d_in[12];
    const float* fc2_b   = (const float*)d_in[13];
    float* out = (float*)d_out;

    int M = in_sizes[0] / C_DIM;   // 4096
    int Nb = 2;
    int T = M / Nb;                // 2048

    float *p_h, *p_qkv, *p_att, *p_x2, *p_m1, *p_part;
    cudaGetSymbolAddress((void**)&p_h,    g_h);
    cudaGetSymbolAddress((void**)&p_qkv,  g_qkv);
    cudaGetSymbolAddress((void**)&p_att,  g_att);
    cudaGetSymbolAddress((void**)&p_x2,   g_x2);
    cudaGetSymbolAddress((void**)&p_m1,   g_m1);
    cudaGetSymbolAddress((void**)&p_part, g_part);

    const int ATT_SMEM = (2 * ATT_SPAN * ATT_LD + ATT_TT * ATT_LD) * 4;
    const int BIG_SMEM = 2 * (128 * PADB + 128 * PADB) * 4;   // 73728
    cudaFuncSetAttribute(attn_kernel,
        cudaFuncAttributeMaxDynamicSharedMemorySize, ATT_SMEM);
    cudaFuncSetAttribute(tc_gemm_big<false>,
        cudaFuncAttributeMaxDynamicSharedMemorySize, BIG_SMEM);
    cudaFuncSetAttribute(tc_gemm_big<true>,
        cudaFuncAttributeMaxDynamicSharedMemorySize, BIG_SMEM);

    const int total4 = M_ROWS * C_DIM / 4;
    const int cblocks = (total4 + 255) / 256;

    // 1) h = LN1(x)
    ln_kernel<<<M, 128>>>(x, norm1_w, norm1_b, p_h);

    // 2) qkv = h @ qkv_w^T + qkv_b        [M,1536]
    tc_gemm_big<false><<<dim3(QKV_DIM / 128, M / 128), 256, BIG_SMEM>>>(
        p_h, qkv_w, qkv_b, p_qkv, M, QKV_DIM, C_DIM);

    // 3) windowed attention -> g_att      [M,512]
    attn_kernel<<<dim3(T / ATT_TT, 8, Nb), 256, ATT_SMEM>>>(
        p_qkv, relbias, p_att, T);

    // 4) proj split-K: partials, then x2 = x + part0+part1 + proj_b
    tc_gemm_sk<<<dim3(C_DIM / 128, M / 64, 2), 256>>>(
        p_att, proj_w, p_part, M, C_DIM, C_DIM);
    sk_combine<<<cblocks, 256>>>(p_part, proj_b, x, p_x2, total4);

    // 5) h = LN2(x2)
    ln_kernel<<<M, 128>>>(p_x2, norm2_w, norm2_b, p_h);

    // 6) m1 = gelu(h @ fc1_w^T + fc1_b)   [M,2048]
    tc_gemm_big<true><<<dim3(HID_DIM / 128, M / 128), 256, BIG_SMEM>>>(
        p_h, fc1_w, fc1_b, p_m1, M, HID_DIM, C_DIM);

    // 7) fc2 split-K: partials, then out = x2 + part0+part1 + fc2_b
    tc_gemm_sk<<<dim3(C_DIM / 128, M / 64, 2), 256>>>(
        p_m1, fc2_w, p_part, M, C_DIM, HID_DIM);
    sk_combine<<<cblocks, 256>>>(p_part, fc2_b, p_x2, out, total4);
}